// round 13
// baseline (speedup 1.0000x reference)
#include <cuda_runtime.h>
#include <cuda_bf16.h>
#include <cstdint>
#include <math.h>

#define N_NODES 50000
#define N_EDGES 800000
#define DDIM    128
#define KDIM    512
#define NROWS_W 384           /* 3*128 combined output cols */

#define AVG_DEG_LOG 2.8332133440562162f  /* log(17) */
#define EPS_STD 1e-5f

#define QSCALE  16128.0f      /* 126*128 : 14-bit quant, limbs |h|<=126, l in [-64,63] */
#define FOLD_F  (128.0f / (16128.0f * 16128.0f))

#define SCAN_BLK  1024
#define SCAN_NBLK ((N_NODES + SCAN_BLK - 1) / SCAN_BLK)   /* 49 */

/* ------------------- scratch (device globals) ---------------------------- */
static __device__ int    g_cnt[N_NODES];           /* zero-init; feat_k re-zeroes */
static __device__ int    g_off[N_NODES + 1];
static __device__ int    g_cur[N_NODES];
static __device__ int    g_csr[N_EDGES];
static __device__ int    g_bsum[64];
static __device__ int    g_boff[64];
static __device__ signed char g_A1[(size_t)N_NODES * KDIM];
static __device__ signed char g_A2[(size_t)N_NODES * KDIM];
static __device__ float  g_sA[N_NODES];
static __device__ float  g_sc[(size_t)N_NODES * 2];
static __device__ signed char g_B1[NROWS_W * KDIM];
static __device__ signed char g_B2[NROWS_W * KDIM];
static __device__ int    g_sBbits;                 /* global max |W| as float bits */

/* ------------------- 1: degree count ------------------------------------- */
__global__ void count_k(const int* __restrict__ index) {
    int e = blockIdx.x * blockDim.x + threadIdx.x;
    if (e < N_EDGES) atomicAdd(&g_cnt[index[e]], 1);
}

/* ------------------- 2a: per-block inclusive scan ------------------------ */
__global__ void scanA_k() {
    __shared__ int sh[32];
    int i    = blockIdx.x * SCAN_BLK + threadIdx.x;
    int lane = threadIdx.x & 31, wid = threadIdx.x >> 5;
    int v = (i < N_NODES) ? g_cnt[i] : 0;
    int incl = v;
    #pragma unroll
    for (int s = 1; s < 32; s <<= 1) {
        int t = __shfl_up_sync(0xFFFFFFFFu, incl, s);
        if (lane >= s) incl += t;
    }
    if (lane == 31) sh[wid] = incl;
    __syncthreads();
    if (wid == 0) {
        int x = sh[lane];
        #pragma unroll
        for (int s = 1; s < 32; s <<= 1) {
            int t = __shfl_up_sync(0xFFFFFFFFu, x, s);
            if (lane >= s) x += t;
        }
        sh[lane] = x;
    }
    __syncthreads();
    if (wid > 0) incl += sh[wid - 1];
    if (i < N_NODES) {
        g_off[i + 1] = incl;
        g_cur[i]     = incl - v;
    }
    if (threadIdx.x == SCAN_BLK - 1) g_bsum[blockIdx.x] = incl;
}

/* ------------------- 2b: scan block sums (1 warp) ------------------------ */
__global__ void scanB_k() {
    int lane = threadIdx.x;
    int carry = 0;
    for (int base = 0; base < SCAN_NBLK; base += 32) {
        int v = (base + lane < SCAN_NBLK) ? g_bsum[base + lane] : 0;
        int incl = v;
        #pragma unroll
        for (int s = 1; s < 32; s <<= 1) {
            int t = __shfl_up_sync(0xFFFFFFFFu, incl, s);
            if (lane >= s) incl += t;
        }
        if (base + lane < SCAN_NBLK) g_boff[base + lane] = carry + incl - v;
        carry += __shfl_sync(0xFFFFFFFFu, incl, 31);
    }
}

/* ------------------- 2c: add back block offsets -------------------------- */
__global__ void scanC_k() {
    int i = blockIdx.x * SCAN_BLK + threadIdx.x;
    if (i < N_NODES) {
        int off = g_boff[blockIdx.x];
        g_off[i + 1] += off;
        g_cur[i]     += off;
    }
}

/* ------------------- 3: scatter edge ids into CSR ------------------------ */
__global__ void scatter_k(const int* __restrict__ index) {
    int e = blockIdx.x * blockDim.x + threadIdx.x;
    if (e < N_EDGES) {
        int n = index[e];
        int p = atomicAdd(&g_cur[n], 1);
        g_csr[p] = e;
    }
}

/* ------------------- 4: features -> int8 2-limb quant -------------------- */
__device__ __forceinline__ void quant_w4(float4 v, float invs,
                                         uint32_t* hw, uint32_t* lw) {
    int i0 = __float2int_rn(v.x * invs);
    int i1 = __float2int_rn(v.y * invs);
    int i2 = __float2int_rn(v.z * invs);
    int i3 = __float2int_rn(v.w * invs);
    int h0 = (i0 + 64) >> 7, h1 = (i1 + 64) >> 7;
    int h2 = (i2 + 64) >> 7, h3 = (i3 + 64) >> 7;
    int l0 = i0 - (h0 << 7), l1 = i1 - (h1 << 7);
    int l2 = i2 - (h2 << 7), l3 = i3 - (h3 << 7);
    *hw = (h0 & 255) | ((h1 & 255) << 8) | ((h2 & 255) << 16) | ((h3 & 255) << 24);
    *lw = (l0 & 255) | ((l1 & 255) << 8) | ((l2 & 255) << 16) | ((l3 & 255) << 24);
}

__global__ void feat_k(const float* __restrict__ x) {
    int gwarp = (blockIdx.x * blockDim.x + threadIdx.x) >> 5;
    int lane  = threadIdx.x & 31;
    if (gwarp >= N_NODES) return;

    int beg = g_off[gwarp], end = g_off[gwarp + 1];
    int deg = end - beg;

    float4 s1 = make_float4(0.f, 0.f, 0.f, 0.f);
    float4 s2 = make_float4(0.f, 0.f, 0.f, 0.f);
    float4 mn = make_float4( 3.4e38f,  3.4e38f,  3.4e38f,  3.4e38f);
    float4 mx = make_float4(-3.4e38f, -3.4e38f, -3.4e38f, -3.4e38f);

    const float4* x4 = (const float4*)x;
    for (int b = beg; b < end; b += 32) {            /* batched csr prefetch */
        int cnt = end - b; if (cnt > 32) cnt = 32;
        int e = 0;
        if (lane < cnt) e = g_csr[b + lane];
        for (int i = 0; i < cnt; i++) {
            int ei = __shfl_sync(0xFFFFFFFFu, e, i);
            float4 v = __ldg(&x4[(size_t)ei * 32 + lane]);
            s1.x += v.x; s1.y += v.y; s1.z += v.z; s1.w += v.w;
            s2.x += v.x*v.x; s2.y += v.y*v.y; s2.z += v.z*v.z; s2.w += v.w*v.w;
            mn.x = fminf(mn.x, v.x); mn.y = fminf(mn.y, v.y);
            mn.z = fminf(mn.z, v.z); mn.w = fminf(mn.w, v.w);
            mx.x = fmaxf(mx.x, v.x); mx.y = fmaxf(mx.y, v.y);
            mx.z = fmaxf(mx.z, v.z); mx.w = fmaxf(mx.w, v.w);
        }
    }

    float degc = (deg > 0) ? (float)deg : 1.0f;
    float inv = 1.0f / degc;
    float4 mean, var, stdv;
    mean.x = s1.x*inv; mean.y = s1.y*inv; mean.z = s1.z*inv; mean.w = s1.w*inv;
    var.x = s2.x*inv - mean.x*mean.x;  var.y = s2.y*inv - mean.y*mean.y;
    var.z = s2.z*inv - mean.z*mean.z;  var.w = s2.w*inv - mean.w*mean.w;
    stdv.x = sqrtf(fmaxf(var.x, 0.f) + EPS_STD);
    stdv.y = sqrtf(fmaxf(var.y, 0.f) + EPS_STD);
    stdv.z = sqrtf(fmaxf(var.z, 0.f) + EPS_STD);
    stdv.w = sqrtf(fmaxf(var.w, 0.f) + EPS_STD);
    if (deg == 0) {
        mn = make_float4(0.f, 0.f, 0.f, 0.f);
        mx = make_float4(0.f, 0.f, 0.f, 0.f);
    }

    /* per-row max |value| over all 512 features */
    float lm = fmaxf(fmaxf(fabsf(mean.x), fabsf(mean.y)),
                     fmaxf(fabsf(mean.z), fabsf(mean.w)));
    lm = fmaxf(lm, fmaxf(fmaxf(fabsf(mn.x), fabsf(mn.y)),
                         fmaxf(fabsf(mn.z), fabsf(mn.w))));
    lm = fmaxf(lm, fmaxf(fmaxf(fabsf(mx.x), fabsf(mx.y)),
                         fmaxf(fabsf(mx.z), fabsf(mx.w))));
    lm = fmaxf(lm, fmaxf(fmaxf(fabsf(stdv.x), fabsf(stdv.y)),
                         fmaxf(fabsf(stdv.z), fabsf(stdv.w))));
    #pragma unroll
    for (int s = 16; s > 0; s >>= 1)
        lm = fmaxf(lm, __shfl_xor_sync(0xFFFFFFFFu, lm, s));
    float sA = fmaxf(lm, 1e-30f);
    float invs = QSCALE / sA;

    size_t base = (size_t)gwarp * KDIM + lane * 4;
    uint32_t hw, lw;
    quant_w4(mean, invs, &hw, &lw);
    *(uint32_t*)(g_A1 + base +   0) = hw;  *(uint32_t*)(g_A2 + base +   0) = lw;
    quant_w4(mn,   invs, &hw, &lw);
    *(uint32_t*)(g_A1 + base + 128) = hw;  *(uint32_t*)(g_A2 + base + 128) = lw;
    quant_w4(mx,   invs, &hw, &lw);
    *(uint32_t*)(g_A1 + base + 256) = hw;  *(uint32_t*)(g_A2 + base + 256) = lw;
    quant_w4(stdv, invs, &hw, &lw);
    *(uint32_t*)(g_A1 + base + 384) = hw;  *(uint32_t*)(g_A2 + base + 384) = lw;

    if (lane == 0) {
        float ld = logf(degc + 1.0f);
        g_sA[gwarp] = sA;
        g_sc[2 * gwarp + 0] = ld / AVG_DEG_LOG;
        g_sc[2 * gwarp + 1] = AVG_DEG_LOG / ld;
        g_cnt[gwarp] = 0;             /* reset for next graph replay */
    }
}

/* ------------------- 5a: global max |W| (atomicMax idempotent) ----------- */
__global__ void wmax_k(const float* __restrict__ W) {
    int i = blockIdx.x * blockDim.x + threadIdx.x;
    float m = 0.f;
    for (; i < 128 * 1536; i += gridDim.x * blockDim.x)
        m = fmaxf(m, fabsf(W[i]));
    #pragma unroll
    for (int s = 16; s > 0; s >>= 1)
        m = fmaxf(m, __shfl_xor_sync(0xFFFFFFFFu, m, s));
    if ((threadIdx.x & 31) == 0)
        atomicMax(&g_sBbits, __float_as_int(fmaxf(m, 1e-30f)));
}

/* ------------------- 5b: quantize W with GLOBAL scale -------------------- */
__global__ void wquant_k(const float* __restrict__ W) {
    int j = blockIdx.x * 4 + (threadIdx.x >> 5);     /* combined col 0..383 */
    int lane = threadIdx.x & 31;
    if (j >= NROWS_W) return;
    const float* col = W + (size_t)(j & 127) * 1536 + (j >> 7) * 512;
    float invs = QSCALE / __int_as_float(g_sBbits);

    #pragma unroll
    for (int t = 0; t < 16; t++) {
        int i = __float2int_rn(col[lane + 32 * t] * invs);
        int h = (i + 64) >> 7;
        int l = i - (h << 7);
        g_B1[(size_t)j * KDIM + lane + 32 * t] = (signed char)h;
        g_B2[(size_t)j * KDIM + lane + 32 * t] = (signed char)l;
    }
}

/* ------------------- 6: IMMA GEMM (s8 2-limb), fused epilogue ------------ */
#define SW64(o) ((o) ^ (((o) >> 3) & 0x30))

__device__ __forceinline__ void ldm_x4(uint32_t* r, uint32_t addr) {
    asm volatile("ldmatrix.sync.aligned.m8n8.x4.shared.b16 {%0,%1,%2,%3}, [%4];"
                 : "=r"(r[0]), "=r"(r[1]), "=r"(r[2]), "=r"(r[3]) : "r"(addr));
}
__device__ __forceinline__ void imma_acc(int* c, const uint32_t* a,
                                         uint32_t b0, uint32_t b1) {
    asm volatile("mma.sync.aligned.m16n8k32.row.col.s32.s8.s8.s32 "
                 "{%0,%1,%2,%3},{%4,%5,%6,%7},{%8,%9},{%0,%1,%2,%3};"
                 : "+r"(c[0]), "+r"(c[1]), "+r"(c[2]), "+r"(c[3])
                 : "r"(a[0]), "r"(a[1]), "r"(a[2]), "r"(a[3]), "r"(b0), "r"(b1));
}
__device__ __forceinline__ void imma_tmp(int* d, const uint32_t* a,
                                         uint32_t b0, uint32_t b1) {
    const int z = 0;
    asm volatile("mma.sync.aligned.m16n8k32.row.col.s32.s8.s8.s32 "
                 "{%0,%1,%2,%3},{%4,%5,%6,%7},{%8,%9},{%10,%10,%10,%10};"
                 : "=r"(d[0]), "=r"(d[1]), "=r"(d[2]), "=r"(d[3])
                 : "r"(a[0]), "r"(a[1]), "r"(a[2]), "r"(a[3]), "r"(b0), "r"(b1),
                   "r"(z));
}
__device__ __forceinline__ void cp16(uint32_t daddr, const void* g, int pred) {
    asm volatile("cp.async.ca.shared.global [%0], [%1], 16, %2;"
                 :: "r"(daddr), "l"(g), "r"(pred ? 16 : 0) : "memory");
}
#define CP_COMMIT() asm volatile("cp.async.commit_group;" ::: "memory")
#define CP_WAIT1()  asm volatile("cp.async.wait_group 1;" ::: "memory")

#define NCHUNK 8               /* K=512 / 64 */
#define SM_A1  0
#define SM_A2  8192
#define SM_B1  16384
#define SM_B2  40960
#define STAGE_BYTES 65536
#define GEMM_SMEM  196608      /* 3 stages */

__device__ __forceinline__ uint32_t smem_u32(const void* p) {
    uint32_t a;
    asm("{ .reg .u64 t; cvta.to.shared.u64 t, %1; cvt.u32.u64 %0, t; }" : "=r"(a) : "l"(p));
    return a;
}

__device__ __forceinline__ void load_stage(char* smem, int t, int row0, int tid) {
    if (t >= NCHUNK) return;
    int k0 = t * 64;
    uint32_t s0 = smem_u32(smem + (t % 3) * STAGE_BYTES);

    #pragma unroll
    for (int j = 0; j < 2; j++) {
        int idx = j * 256 + tid;
        int row = idx >> 2, c = idx & 3;
        int gr = row0 + row;
        uint32_t sw = SW64((uint32_t)(row * 64 + c * 16));
        size_t gofs = (size_t)gr * KDIM + k0 + c * 16;
        cp16(s0 + SM_A1 + sw, g_A1 + gofs, gr < N_NODES);
        cp16(s0 + SM_A2 + sw, g_A2 + gofs, gr < N_NODES);
    }
    #pragma unroll
    for (int j = 0; j < 6; j++) {
        int idx = j * 256 + tid;
        int row = idx >> 2, c = idx & 3;
        uint32_t sw = SW64((uint32_t)(row * 64 + c * 16));
        size_t gofs = (size_t)row * KDIM + k0 + c * 16;
        cp16(s0 + SM_B1 + sw, g_B1 + gofs, 1);
        cp16(s0 + SM_B2 + sw, g_B2 + gofs, 1);
    }
}

__global__ void __launch_bounds__(256, 1) gemm_imma_k(const float* __restrict__ bias,
                                                      float* __restrict__ out) {
    extern __shared__ char smem[];
    int tid  = threadIdx.x;
    int warp = tid >> 5, lane = tid & 31;
    int wm = warp >> 1, wn = warp & 1;     /* 4 x 2 warp grid, warp tile 32x64 */
    int row0 = blockIdx.x * 128;

    /* per-thread fold factors: rowfac[nb][mt][hi] = sA*F * {1,samp,satt} */
    float rowfac[3][2][2];
    #pragma unroll
    for (int mt = 0; mt < 2; mt++)
        #pragma unroll
        for (int hi = 0; hi < 2; hi++) {
            int r = row0 + wm * 32 + mt * 16 + hi * 8 + (lane >> 2);
            float sa = (r < N_NODES) ? g_sA[r] * FOLD_F : 0.f;
            float sp = (r < N_NODES) ? g_sc[2 * r]     : 0.f;
            float st = (r < N_NODES) ? g_sc[2 * r + 1] : 0.f;
            rowfac[0][mt][hi] = sa;
            rowfac[1][mt][hi] = sa * sp;
            rowfac[2][mt][hi] = sa * st;
        }
    float sBg = __int_as_float(g_sBbits);   /* global B scale */

    int   acc[2][8][4];
    float oacc[2][8][4];
    #pragma unroll
    for (int i = 0; i < 2; i++)
        #pragma unroll
        for (int j = 0; j < 8; j++)
            #pragma unroll
            for (int k = 0; k < 4; k++) { acc[i][j][k] = 0; oacc[i][j][k] = 0.f; }

    load_stage(smem, 0, row0, tid);
    CP_COMMIT();
    load_stage(smem, 1, row0, tid);
    CP_COMMIT();

    for (int t = 0; t < NCHUNK; t++) {
        CP_WAIT1();
        __syncthreads();
        load_stage(smem, t + 2, row0, tid);
        CP_COMMIT();

        uint32_t s0 = smem_u32(smem + (t % 3) * STAGE_BYTES);

        uint32_t af1[2][2][4], af2[2][2][4];
        #pragma unroll
        for (int kt = 0; kt < 2; kt++)
            #pragma unroll
            for (int mt = 0; mt < 2; mt++) {
                int r = wm * 32 + mt * 16 + (lane & 15);
                uint32_t sw = SW64((uint32_t)(r * 64 + kt * 32 + ((lane >> 4) * 16)));
                ldm_x4(af1[kt][mt], s0 + SM_A1 + sw);
                ldm_x4(af2[kt][mt], s0 + SM_A2 + sw);
            }

        #pragma unroll
        for (int nb = 0; nb < 3; nb++) {
            #pragma unroll
            for (int kt = 0; kt < 2; kt++) {
                #pragma unroll
                for (int n4 = 0; n4 < 4; n4++) {
                    int n = nb * 128 + wn * 64 + n4 * 16 + (lane & 15);
                    uint32_t sw = SW64((uint32_t)(n * 64 + kt * 32 + ((lane >> 4) * 16)));
                    uint32_t b1[4], b2[4];
                    ldm_x4(b1, s0 + SM_B1 + sw);
                    ldm_x4(b2, s0 + SM_B2 + sw);
                    #pragma unroll
                    for (int mt = 0; mt < 2; mt++)
                        #pragma unroll
                        for (int hi = 0; hi < 2; hi++) {
                            int nt = n4 * 2 + hi;
                            int tmp[4];
                            imma_tmp(tmp, af1[kt][mt], b1[hi], b1[hi + 2]);
                            acc[mt][nt][0] += tmp[0] << 7;
                            acc[mt][nt][1] += tmp[1] << 7;
                            acc[mt][nt][2] += tmp[2] << 7;
                            acc[mt][nt][3] += tmp[3] << 7;
                            imma_acc(acc[mt][nt], af1[kt][mt], b2[hi], b2[hi + 2]);
                            imma_acc(acc[mt][nt], af2[kt][mt], b1[hi], b1[hi + 2]);
                        }
                }
            }
            /* fold this block's chunk-partial into oacc, reset acc */
            #pragma unroll
            for (int mt = 0; mt < 2; mt++)
                #pragma unroll
                for (int nt = 0; nt < 8; nt++) {
                    float rf0 = rowfac[nb][mt][0], rf1 = rowfac[nb][mt][1];
                    oacc[mt][nt][0] += rf0 * (float)acc[mt][nt][0];
                    oacc[mt][nt][1] += rf0 * (float)acc[mt][nt][1];
                    oacc[mt][nt][2] += rf1 * (float)acc[mt][nt][2];
                    oacc[mt][nt][3] += rf1 * (float)acc[mt][nt][3];
                    acc[mt][nt][0] = 0; acc[mt][nt][1] = 0;
                    acc[mt][nt][2] = 0; acc[mt][nt][3] = 0;
                }
        }
    }

    /* write out: apply global B scale + bias */
    #pragma unroll
    for (int mt = 0; mt < 2; mt++)
        #pragma unroll
        for (int nt = 0; nt < 8; nt++) {
            int r = row0 + wm * 32 + mt * 16 + (lane >> 2);
            int c = wn * 64 + nt * 8 + (lane & 3) * 2;
            float b0 = bias[c], b1 = bias[c + 1];
            if (r < N_NODES)
                *(float2*)&out[(size_t)r * DDIM + c] =
                    make_float2(oacc[mt][nt][0] * sBg + b0,
                                oacc[mt][nt][1] * sBg + b1);
            if (r + 8 < N_NODES)
                *(float2*)&out[(size_t)(r + 8) * DDIM + c] =
                    make_float2(oacc[mt][nt][2] * sBg + b0,
                                oacc[mt][nt][3] * sBg + b1);
        }
}

/* ------------------- launch ---------------------------------------------- */
extern "C" void kernel_launch(void* const* d_in, const int* in_sizes, int n_in,
                              void* d_out, int out_size) {
    const float* x     = (const float*)d_in[0];
    const int*   index = (const int*)d_in[1];
    const float* W     = (const float*)d_in[2];
    const float* b     = (const float*)d_in[3];
    float*       out   = (float*)d_out;
    (void)in_sizes; (void)n_in; (void)out_size;

    cudaFuncSetAttribute(gemm_imma_k, cudaFuncAttributeMaxDynamicSharedMemorySize,
                         GEMM_SMEM);

    count_k<<<(N_EDGES + 255) / 256, 256>>>(index);
    scanA_k<<<SCAN_NBLK, SCAN_BLK>>>();
    scanB_k<<<1, 32>>>();
    scanC_k<<<SCAN_NBLK, SCAN_BLK>>>();
    scatter_k<<<(N_EDGES + 255) / 256, 256>>>(index);
    feat_k<<<(N_NODES * 32 + 255) / 256, 256>>>(x);
    wmax_k<<<192, 256>>>(W);
    wquant_k<<<(NROWS_W + 3) / 4, 128>>>(W);
    gemm_imma_k<<<(N_NODES + 127) / 128, 256, GEMM_SMEM>>>(b, out);
}

// round 14
// speedup vs baseline: 2.0531x; 2.0531x over previous
#include <cuda_runtime.h>
#include <cuda_fp16.h>
#include <cstdint>
#include <math.h>

#define N_NODES 50000
#define N_EDGES 800000
#define DDIM    128
#define KDIM    512
#define NROWS_W 384           /* 3*128 combined output cols */

#define AVG_DEG_LOG 2.8332133440562162f  /* log(17) */
#define EPS_STD 1e-5f

#define SCAN_BLK  1024
#define SCAN_NBLK ((N_NODES + SCAN_BLK - 1) / SCAN_BLK)   /* 49 */

/* ------------------- scratch (device globals) ---------------------------- */
static __device__ int    g_cnt[N_NODES];           /* zero-init; feat_k re-zeroes */
static __device__ int    g_off[N_NODES + 1];
static __device__ int    g_cur[N_NODES];
static __device__ int    g_csr[N_EDGES];
static __device__ int    g_bsum[64];
static __device__ int    g_boff[64];
static __device__ __half g_A[(size_t)N_NODES * KDIM];    /* single-limb f16 */
static __device__ float  g_sc[(size_t)N_NODES * 2];
static __device__ __half g_Wh[NROWS_W * KDIM];
static __device__ __half g_Wl[NROWS_W * KDIM];

/* ------------------- 1: degree count ------------------------------------- */
__global__ void count_k(const int* __restrict__ index) {
    int e = blockIdx.x * blockDim.x + threadIdx.x;
    if (e < N_EDGES) atomicAdd(&g_cnt[index[e]], 1);
}

/* ------------------- 2a: per-block inclusive scan ------------------------ */
__global__ void scanA_k() {
    __shared__ int sh[32];
    int i    = blockIdx.x * SCAN_BLK + threadIdx.x;
    int lane = threadIdx.x & 31, wid = threadIdx.x >> 5;
    int v = (i < N_NODES) ? g_cnt[i] : 0;
    int incl = v;
    #pragma unroll
    for (int s = 1; s < 32; s <<= 1) {
        int t = __shfl_up_sync(0xFFFFFFFFu, incl, s);
        if (lane >= s) incl += t;
    }
    if (lane == 31) sh[wid] = incl;
    __syncthreads();
    if (wid == 0) {
        int x = sh[lane];
        #pragma unroll
        for (int s = 1; s < 32; s <<= 1) {
            int t = __shfl_up_sync(0xFFFFFFFFu, x, s);
            if (lane >= s) x += t;
        }
        sh[lane] = x;
    }
    __syncthreads();
    if (wid > 0) incl += sh[wid - 1];
    if (i < N_NODES) {
        g_off[i + 1] = incl;
        g_cur[i]     = incl - v;
    }
    if (threadIdx.x == SCAN_BLK - 1) g_bsum[blockIdx.x] = incl;
}

/* ------------------- 2b: scan block sums (1 warp) ------------------------ */
__global__ void scanB_k() {
    int lane = threadIdx.x;
    int carry = 0;
    for (int base = 0; base < SCAN_NBLK; base += 32) {
        int v = (base + lane < SCAN_NBLK) ? g_bsum[base + lane] : 0;
        int incl = v;
        #pragma unroll
        for (int s = 1; s < 32; s <<= 1) {
            int t = __shfl_up_sync(0xFFFFFFFFu, incl, s);
            if (lane >= s) incl += t;
        }
        if (base + lane < SCAN_NBLK) g_boff[base + lane] = carry + incl - v;
        carry += __shfl_sync(0xFFFFFFFFu, incl, 31);
    }
}

/* ------------------- 2c: add back block offsets -------------------------- */
__global__ void scanC_k() {
    int i = blockIdx.x * SCAN_BLK + threadIdx.x;
    if (i < N_NODES) {
        int off = g_boff[blockIdx.x];
        g_off[i + 1] += off;
        g_cur[i]     += off;
    }
}

/* ------------------- 3: scatter edge ids into CSR ------------------------ */
__global__ void scatter_k(const int* __restrict__ index) {
    int e = blockIdx.x * blockDim.x + threadIdx.x;
    if (e < N_EDGES) {
        int n = index[e];
        int p = atomicAdd(&g_cur[n], 1);
        g_csr[p] = e;
    }
}

/* ------------------- 4: features -> natural f16 -------------------------- */
__device__ __forceinline__ void st_h4(float4 v, __half* p) {
    __half2 h01 = __floats2half2_rn(v.x, v.y);
    __half2 h23 = __floats2half2_rn(v.z, v.w);
    uint2 u;
    u.x = *(uint32_t*)&h01;
    u.y = *(uint32_t*)&h23;
    *(uint2*)p = u;
}

__global__ void feat_k(const float* __restrict__ x) {
    int gwarp = (blockIdx.x * blockDim.x + threadIdx.x) >> 5;
    int lane  = threadIdx.x & 31;
    if (gwarp >= N_NODES) return;

    int beg = g_off[gwarp], end = g_off[gwarp + 1];
    int deg = end - beg;

    float4 s1 = make_float4(0.f, 0.f, 0.f, 0.f);
    float4 s2 = make_float4(0.f, 0.f, 0.f, 0.f);
    float4 mn = make_float4( 3.4e38f,  3.4e38f,  3.4e38f,  3.4e38f);
    float4 mx = make_float4(-3.4e38f, -3.4e38f, -3.4e38f, -3.4e38f);

    const float4* x4 = (const float4*)x;
    for (int b = beg; b < end; b += 32) {            /* batched csr prefetch */
        int cnt = end - b; if (cnt > 32) cnt = 32;
        int e = 0;
        if (lane < cnt) e = g_csr[b + lane];
        for (int i = 0; i < cnt; i++) {
            int ei = __shfl_sync(0xFFFFFFFFu, e, i);
            float4 v = __ldg(&x4[(size_t)ei * 32 + lane]);
            s1.x += v.x; s1.y += v.y; s1.z += v.z; s1.w += v.w;
            s2.x += v.x*v.x; s2.y += v.y*v.y; s2.z += v.z*v.z; s2.w += v.w*v.w;
            mn.x = fminf(mn.x, v.x); mn.y = fminf(mn.y, v.y);
            mn.z = fminf(mn.z, v.z); mn.w = fminf(mn.w, v.w);
            mx.x = fmaxf(mx.x, v.x); mx.y = fmaxf(mx.y, v.y);
            mx.z = fmaxf(mx.z, v.z); mx.w = fmaxf(mx.w, v.w);
        }
    }

    float degc = (deg > 0) ? (float)deg : 1.0f;
    float inv = 1.0f / degc;
    float4 mean, var, stdv;
    mean.x = s1.x*inv; mean.y = s1.y*inv; mean.z = s1.z*inv; mean.w = s1.w*inv;
    var.x = s2.x*inv - mean.x*mean.x;  var.y = s2.y*inv - mean.y*mean.y;
    var.z = s2.z*inv - mean.z*mean.z;  var.w = s2.w*inv - mean.w*mean.w;
    stdv.x = sqrtf(fmaxf(var.x, 0.f) + EPS_STD);
    stdv.y = sqrtf(fmaxf(var.y, 0.f) + EPS_STD);
    stdv.z = sqrtf(fmaxf(var.z, 0.f) + EPS_STD);
    stdv.w = sqrtf(fmaxf(var.w, 0.f) + EPS_STD);
    if (deg == 0) {
        mn = make_float4(0.f, 0.f, 0.f, 0.f);
        mx = make_float4(0.f, 0.f, 0.f, 0.f);
    }

    size_t base = (size_t)gwarp * KDIM + lane * 4;
    st_h4(mean, g_A + base +   0);
    st_h4(mn,   g_A + base + 128);
    st_h4(mx,   g_A + base + 256);
    st_h4(stdv, g_A + base + 384);

    if (lane == 0) {
        float ld = logf(degc + 1.0f);
        g_sc[2 * gwarp + 0] = ld / AVG_DEG_LOG;
        g_sc[2 * gwarp + 1] = AVG_DEG_LOG / ld;
        g_cnt[gwarp] = 0;             /* reset for next graph replay */
    }
}

/* ------------------- 5: split W into f16 hi/lo --------------------------- */
__global__ void wsplit_k(const float* __restrict__ W) {
    int idx = blockIdx.x * blockDim.x + threadIdx.x;
    if (idx >= NROWS_W * KDIM) return;
    int j = idx >> 9, k = idx & 511;
    float v = W[(size_t)(j & 127) * 1536 + (j >> 7) * 512 + k];
    __half h = __float2half_rn(v);
    g_Wh[idx] = h;
    g_Wl[idx] = __float2half_rn(v - __half2float(h));
}

/* ------------------- 6: HMMA f16 GEMM, fused epilogue --------------------
 * 16 chunks of K=32.  Per chunk: stage holds A (128x32 f16) + Wh,Wl
 * (384x32 f16).  Per output block nb: acc += A*Bh + A*Bl; fold into oacc
 * with per-row scale {1, samp, satt}.  3-stage cp.async pipeline.
 */
#define SW64(o) ((o) ^ (((o) >> 3) & 0x30))

__device__ __forceinline__ void ldm_x4(uint32_t* r, uint32_t addr) {
    asm volatile("ldmatrix.sync.aligned.m8n8.x4.shared.b16 {%0,%1,%2,%3}, [%4];"
                 : "=r"(r[0]), "=r"(r[1]), "=r"(r[2]), "=r"(r[3]) : "r"(addr));
}
__device__ __forceinline__ void mma16816(float* c, const uint32_t* a,
                                         uint32_t b0, uint32_t b1) {
    asm volatile("mma.sync.aligned.m16n8k16.row.col.f32.f16.f16.f32 "
                 "{%0,%1,%2,%3},{%4,%5,%6,%7},{%8,%9},{%0,%1,%2,%3};"
                 : "+f"(c[0]), "+f"(c[1]), "+f"(c[2]), "+f"(c[3])
                 : "r"(a[0]), "r"(a[1]), "r"(a[2]), "r"(a[3]), "r"(b0), "r"(b1));
}
__device__ __forceinline__ void cp16(uint32_t daddr, const void* g, int pred) {
    asm volatile("cp.async.ca.shared.global [%0], [%1], 16, %2;"
                 :: "r"(daddr), "l"(g), "r"(pred ? 16 : 0) : "memory");
}
#define CP_COMMIT() asm volatile("cp.async.commit_group;" ::: "memory")
#define CP_WAIT1()  asm volatile("cp.async.wait_group 1;" ::: "memory")

#define NCHUNK 16              /* K=512 / 32 */
#define SM_A   0
#define SM_BH  8192
#define SM_BL  32768
#define STAGE_BYTES 57344      /* A(8K) + Bh(24K) + Bl(24K) */
#define GEMM_SMEM  172032      /* 3 stages */

__device__ __forceinline__ uint32_t smem_u32(const void* p) {
    uint32_t a;
    asm("{ .reg .u64 t; cvta.to.shared.u64 t, %1; cvt.u32.u64 %0, t; }" : "=r"(a) : "l"(p));
    return a;
}

__device__ __forceinline__ void load_stage(char* smem, int t, int row0, int tid) {
    if (t >= NCHUNK) return;
    int k0 = t * 32;               /* f16 element offset within 512 */
    uint32_t s0 = smem_u32(smem + (t % 3) * STAGE_BYTES);

    /* A: 128 rows x 64B, 512 x 16B segs */
    #pragma unroll
    for (int j = 0; j < 2; j++) {
        int idx = j * 256 + tid;
        int row = idx >> 2, c = idx & 3;
        int gr = row0 + row;
        uint32_t sw = SW64((uint32_t)(row * 64 + c * 16));
        cp16(s0 + SM_A + sw, g_A + (size_t)gr * KDIM + k0 + c * 8, gr < N_NODES);
    }
    /* B hi/lo: 384 rows x 64B, 1536 x 16B segs each */
    #pragma unroll
    for (int j = 0; j < 6; j++) {
        int idx = j * 256 + tid;
        int row = idx >> 2, c = idx & 3;
        uint32_t sw = SW64((uint32_t)(row * 64 + c * 16));
        size_t gofs = (size_t)row * KDIM + k0 + c * 8;
        cp16(s0 + SM_BH + sw, g_Wh + gofs, 1);
        cp16(s0 + SM_BL + sw, g_Wl + gofs, 1);
    }
}

__global__ void __launch_bounds__(256, 1) gemm_mma_k(const float* __restrict__ bias,
                                                     float* __restrict__ out) {
    extern __shared__ char smem[];
    int tid  = threadIdx.x;
    int warp = tid >> 5, lane = tid & 31;
    int wm = warp >> 1, wn = warp & 1;     /* 4 x 2 warp grid, warp tile 32x64 */
    int row0 = blockIdx.x * 128;

    /* per-thread row scale factors for fold */
    float samp_r[2][2], satt_r[2][2];
    #pragma unroll
    for (int mt = 0; mt < 2; mt++)
        #pragma unroll
        for (int hi = 0; hi < 2; hi++) {
            int r = row0 + wm * 32 + mt * 16 + hi * 8 + (lane >> 2);
            samp_r[mt][hi] = (r < N_NODES) ? g_sc[2 * r] : 0.f;
            satt_r[mt][hi] = (r < N_NODES) ? g_sc[2 * r + 1] : 0.f;
        }

    float acc[2][8][4], oacc[2][8][4];
    #pragma unroll
    for (int i = 0; i < 2; i++)
        #pragma unroll
        for (int j = 0; j < 8; j++)
            #pragma unroll
            for (int k = 0; k < 4; k++) { acc[i][j][k] = 0.f; oacc[i][j][k] = 0.f; }

    load_stage(smem, 0, row0, tid);
    CP_COMMIT();
    load_stage(smem, 1, row0, tid);
    CP_COMMIT();

    for (int t = 0; t < NCHUNK; t++) {
        CP_WAIT1();
        __syncthreads();
        load_stage(smem, t + 2, row0, tid);
        CP_COMMIT();

        uint32_t s0 = smem_u32(smem + (t % 3) * STAGE_BYTES);

        /* A fragments: both kt halves, resident for the whole chunk */
        uint32_t af[2][2][4];
        #pragma unroll
        for (int kt = 0; kt < 2; kt++)
            #pragma unroll
            for (int mt = 0; mt < 2; mt++) {
                int r = wm * 32 + mt * 16 + (lane & 15);
                uint32_t sw = SW64((uint32_t)(r * 64 + kt * 32 + ((lane >> 4) * 16)));
                ldm_x4(af[kt][mt], s0 + SM_A + sw);
            }

        #pragma unroll
        for (int nb = 0; nb < 3; nb++) {
            #pragma unroll
            for (int kt = 0; kt < 2; kt++) {
                #pragma unroll
                for (int n4 = 0; n4 < 4; n4++) {
                    int n = nb * 128 + wn * 64 + n4 * 16 + (lane & 15);
                    uint32_t sw = SW64((uint32_t)(n * 64 + kt * 32 + ((lane >> 4) * 16)));
                    uint32_t bh[4], bl[4];
                    ldm_x4(bh, s0 + SM_BH + sw);
                    ldm_x4(bl, s0 + SM_BL + sw);
                    #pragma unroll
                    for (int mt = 0; mt < 2; mt++)
                        #pragma unroll
                        for (int hi = 0; hi < 2; hi++) {
                            int nt = n4 * 2 + hi;
                            mma16816(acc[mt][nt], af[kt][mt], bh[hi], bh[hi + 2]);
                            mma16816(acc[mt][nt], af[kt][mt], bl[hi], bl[hi + 2]);
                        }
                }
            }
            /* fold this block's chunk-partial into oacc, reset acc */
            #pragma unroll
            for (int mt = 0; mt < 2; mt++)
                #pragma unroll
                for (int nt = 0; nt < 8; nt++) {
                    float s0f, s1f;
                    if (nb == 0)      { s0f = 1.f;            s1f = 1.f; }
                    else if (nb == 1) { s0f = samp_r[mt][0];  s1f = samp_r[mt][1]; }
                    else              { s0f = satt_r[mt][0];  s1f = satt_r[mt][1]; }
                    oacc[mt][nt][0] += s0f * acc[mt][nt][0];
                    oacc[mt][nt][1] += s0f * acc[mt][nt][1];
                    oacc[mt][nt][2] += s1f * acc[mt][nt][2];
                    oacc[mt][nt][3] += s1f * acc[mt][nt][3];
                    acc[mt][nt][0] = 0.f; acc[mt][nt][1] = 0.f;
                    acc[mt][nt][2] = 0.f; acc[mt][nt][3] = 0.f;
                }
        }
    }

    /* write out + bias */
    #pragma unroll
    for (int mt = 0; mt < 2; mt++)
        #pragma unroll
        for (int nt = 0; nt < 8; nt++) {
            int r = row0 + wm * 32 + mt * 16 + (lane >> 2);
            int c = wn * 64 + nt * 8 + (lane & 3) * 2;
            float b0 = bias[c], b1 = bias[c + 1];
            if (r < N_NODES)
                *(float2*)&out[(size_t)r * DDIM + c] =
                    make_float2(oacc[mt][nt][0] + b0, oacc[mt][nt][1] + b1);
            if (r + 8 < N_NODES)
                *(float2*)&out[(size_t)(r + 8) * DDIM + c] =
                    make_float2(oacc[mt][nt][2] + b0, oacc[mt][nt][3] + b1);
        }
}

/* ------------------- launch ---------------------------------------------- */
extern "C" void kernel_launch(void* const* d_in, const int* in_sizes, int n_in,
                              void* d_out, int out_size) {
    const float* x     = (const float*)d_in[0];
    const int*   index = (const int*)d_in[1];
    const float* W     = (const float*)d_in[2];
    const float* b     = (const float*)d_in[3];
    float*       out   = (float*)d_out;
    (void)in_sizes; (void)n_in; (void)out_size;

    cudaFuncSetAttribute(gemm_mma_k, cudaFuncAttributeMaxDynamicSharedMemorySize,
                         GEMM_SMEM);

    count_k<<<(N_EDGES + 255) / 256, 256>>>(index);
    scanA_k<<<SCAN_NBLK, SCAN_BLK>>>();
    scanB_k<<<1, 32>>>();
    scanC_k<<<SCAN_NBLK, SCAN_BLK>>>();
    scatter_k<<<(N_EDGES + 255) / 256, 256>>>(index);
    feat_k<<<(N_NODES * 32 + 255) / 256, 256>>>(x);
    wsplit_k<<<(NROWS_W * KDIM + 255) / 256, 256>>>(W);
    gemm_mma_k<<<(N_NODES + 127) / 128, 256, GEMM_SMEM>>>(b, out);
}

// round 17
// speedup vs baseline: 2.9043x; 1.4146x over previous
#include <cuda_runtime.h>
#include <cuda_fp16.h>
#include <cstdint>
#include <math.h>

#define N_NODES 50000
#define N_EDGES 800000
#define DDIM    128
#define KDIM    512
#define NROWS_W 384           /* 3*128 combined output cols */

#define AVG_DEG_LOG 2.8332133440562162f  /* log(17) */
#define EPS_STD 1e-5f

#define SCAN_BLK  1024
#define SCAN_NBLK ((N_NODES + SCAN_BLK - 1) / SCAN_BLK)   /* 49 */

/* ------------------- scratch (device globals) ---------------------------- */
static __device__ int    g_cnt[N_NODES];           /* zero-init; feat_k re-zeroes */
static __device__ int    g_off[N_NODES + 1];
static __device__ int    g_cur[N_NODES];
static __device__ int    g_csr[N_EDGES];
static __device__ int    g_bsum[64];
static __device__ int    g_boff[64];
static __device__ __half g_A[(size_t)N_NODES * KDIM];    /* single-limb f16 */
static __device__ float  g_sc[(size_t)N_NODES * 2];
static __device__ __half g_W[NROWS_W * KDIM];            /* single-limb f16 */

/* ------------------- 1: degree count ------------------------------------- */
__global__ void count_k(const int* __restrict__ index) {
    int e = blockIdx.x * blockDim.x + threadIdx.x;
    if (e < N_EDGES) atomicAdd(&g_cnt[index[e]], 1);
}

/* ------------------- 2a: per-block inclusive scan ------------------------ */
__global__ void scanA_k() {
    __shared__ int sh[32];
    int i    = blockIdx.x * SCAN_BLK + threadIdx.x;
    int lane = threadIdx.x & 31, wid = threadIdx.x >> 5;
    int v = (i < N_NODES) ? g_cnt[i] : 0;
    int incl = v;
    #pragma unroll
    for (int s = 1; s < 32; s <<= 1) {
        int t = __shfl_up_sync(0xFFFFFFFFu, incl, s);
        if (lane >= s) incl += t;
    }
    if (lane == 31) sh[wid] = incl;
    __syncthreads();
    if (wid == 0) {
        int x = sh[lane];
        #pragma unroll
        for (int s = 1; s < 32; s <<= 1) {
            int t = __shfl_up_sync(0xFFFFFFFFu, x, s);
            if (lane >= s) x += t;
        }
        sh[lane] = x;
    }
    __syncthreads();
    if (wid > 0) incl += sh[wid - 1];
    if (i < N_NODES) {
        g_off[i + 1] = incl;
        g_cur[i]     = incl - v;
    }
    if (threadIdx.x == SCAN_BLK - 1) g_bsum[blockIdx.x] = incl;
}

/* ------------------- 2b: scan block sums (1 warp) ------------------------ */
__global__ void scanB_k() {
    int lane = threadIdx.x;
    int carry = 0;
    for (int base = 0; base < SCAN_NBLK; base += 32) {
        int v = (base + lane < SCAN_NBLK) ? g_bsum[base + lane] : 0;
        int incl = v;
        #pragma unroll
        for (int s = 1; s < 32; s <<= 1) {
            int t = __shfl_up_sync(0xFFFFFFFFu, incl, s);
            if (lane >= s) incl += t;
        }
        if (base + lane < SCAN_NBLK) g_boff[base + lane] = carry + incl - v;
        carry += __shfl_sync(0xFFFFFFFFu, incl, 31);
    }
}

/* ------------------- 2c: add back block offsets -------------------------- */
__global__ void scanC_k() {
    int i = blockIdx.x * SCAN_BLK + threadIdx.x;
    if (i < N_NODES) {
        int off = g_boff[blockIdx.x];
        g_off[i + 1] += off;
        g_cur[i]     += off;
    }
}

/* ------------------- 3: scatter edge ids into CSR ------------------------ */
__global__ void scatter_k(const int* __restrict__ index) {
    int e = blockIdx.x * blockDim.x + threadIdx.x;
    if (e < N_EDGES) {
        int n = index[e];
        int p = atomicAdd(&g_cur[n], 1);
        g_csr[p] = e;
    }
}

/* ------------------- 4: features -> natural f16 -------------------------- */
__device__ __forceinline__ void st_h4(float4 v, __half* p) {
    __half2 h01 = __floats2half2_rn(v.x, v.y);
    __half2 h23 = __floats2half2_rn(v.z, v.w);
    uint2 u;
    u.x = *(uint32_t*)&h01;
    u.y = *(uint32_t*)&h23;
    *(uint2*)p = u;
}

__global__ void feat_k(const float* __restrict__ x) {
    int gwarp = (blockIdx.x * blockDim.x + threadIdx.x) >> 5;
    int lane  = threadIdx.x & 31;
    if (gwarp >= N_NODES) return;

    int beg = g_off[gwarp], end = g_off[gwarp + 1];
    int deg = end - beg;

    float4 s1 = make_float4(0.f, 0.f, 0.f, 0.f);
    float4 s2 = make_float4(0.f, 0.f, 0.f, 0.f);
    float4 mn = make_float4( 3.4e38f,  3.4e38f,  3.4e38f,  3.4e38f);
    float4 mx = make_float4(-3.4e38f, -3.4e38f, -3.4e38f, -3.4e38f);

    const float4* x4 = (const float4*)x;
    for (int b = beg; b < end; b += 32) {            /* batched csr prefetch */
        int cnt = end - b; if (cnt > 32) cnt = 32;
        int e = 0;
        if (lane < cnt) e = g_csr[b + lane];
        for (int i = 0; i < cnt; i++) {
            int ei = __shfl_sync(0xFFFFFFFFu, e, i);
            float4 v = __ldg(&x4[(size_t)ei * 32 + lane]);
            s1.x += v.x; s1.y += v.y; s1.z += v.z; s1.w += v.w;
            s2.x += v.x*v.x; s2.y += v.y*v.y; s2.z += v.z*v.z; s2.w += v.w*v.w;
            mn.x = fminf(mn.x, v.x); mn.y = fminf(mn.y, v.y);
            mn.z = fminf(mn.z, v.z); mn.w = fminf(mn.w, v.w);
            mx.x = fmaxf(mx.x, v.x); mx.y = fmaxf(mx.y, v.y);
            mx.z = fmaxf(mx.z, v.z); mx.w = fmaxf(mx.w, v.w);
        }
    }

    float degc = (deg > 0) ? (float)deg : 1.0f;
    float inv = 1.0f / degc;
    float4 mean, var, stdv;
    mean.x = s1.x*inv; mean.y = s1.y*inv; mean.z = s1.z*inv; mean.w = s1.w*inv;
    var.x = s2.x*inv - mean.x*mean.x;  var.y = s2.y*inv - mean.y*mean.y;
    var.z = s2.z*inv - mean.z*mean.z;  var.w = s2.w*inv - mean.w*mean.w;
    stdv.x = sqrtf(fmaxf(var.x, 0.f) + EPS_STD);
    stdv.y = sqrtf(fmaxf(var.y, 0.f) + EPS_STD);
    stdv.z = sqrtf(fmaxf(var.z, 0.f) + EPS_STD);
    stdv.w = sqrtf(fmaxf(var.w, 0.f) + EPS_STD);
    if (deg == 0) {
        mn = make_float4(0.f, 0.f, 0.f, 0.f);
        mx = make_float4(0.f, 0.f, 0.f, 0.f);
    }

    size_t base = (size_t)gwarp * KDIM + lane * 4;
    st_h4(mean, g_A + base +   0);
    st_h4(mn,   g_A + base + 128);
    st_h4(mx,   g_A + base + 256);
    st_h4(stdv, g_A + base + 384);

    if (lane == 0) {
        float ld = logf(degc + 1.0f);
        g_sc[2 * gwarp + 0] = ld / AVG_DEG_LOG;
        g_sc[2 * gwarp + 1] = AVG_DEG_LOG / ld;
        g_cnt[gwarp] = 0;             /* reset for next graph replay */
    }
}

/* ------------------- 5: cast W to f16 (combined layout) ------------------ */
__global__ void wsplit_k(const float* __restrict__ W) {
    int idx = blockIdx.x * blockDim.x + threadIdx.x;
    if (idx >= NROWS_W * KDIM) return;
    int j = idx >> 9, k = idx & 511;
    g_W[idx] = __float2half_rn(W[(size_t)(j & 127) * 1536 + (j >> 7) * 512 + k]);
}

/* ------------------- 6: HMMA f16 GEMM, fused epilogue --------------------
 * 16 chunks of K=32.  Per chunk: stage holds A (128x32 f16) + W
 * (384x32 f16).  Per output block nb: acc += A*B; fold into oacc with
 * per-row scale {1, samp, satt}.  3-stage cp.async pipeline.
 */
#define SW64(o) ((o) ^ (((o) >> 3) & 0x30))

__device__ __forceinline__ void ldm_x4(uint32_t* r, uint32_t addr) {
    asm volatile("ldmatrix.sync.aligned.m8n8.x4.shared.b16 {%0,%1,%2,%3}, [%4];"
                 : "=r"(r[0]), "=r"(r[1]), "=r"(r[2]), "=r"(r[3]) : "r"(addr));
}
__device__ __forceinline__ void mma16816(float* c, const uint32_t* a,
                                         uint32_t b0, uint32_t b1) {
    asm volatile("mma.sync.aligned.m16n8k16.row.col.f32.f16.f16.f32 "
                 "{%0,%1,%2,%3},{%4,%5,%6,%7},{%8,%9},{%0,%1,%2,%3};"
                 : "+f"(c[0]), "+f"(c[1]), "+f"(c[2]), "+f"(c[3])
                 : "r"(a[0]), "r"(a[1]), "r"(a[2]), "r"(a[3]), "r"(b0), "r"(b1));
}
__device__ __forceinline__ void cp16(uint32_t daddr, const void* g, int pred) {
    asm volatile("cp.async.ca.shared.global [%0], [%1], 16, %2;"
                 :: "r"(daddr), "l"(g), "r"(pred ? 16 : 0) : "memory");
}
#define CP_COMMIT() asm volatile("cp.async.commit_group;" ::: "memory")
#define CP_WAIT1()  asm volatile("cp.async.wait_group 1;" ::: "memory")

#define NCHUNK 16              /* K=512 / 32 */
#define SM_A   0
#define SM_B   8192
#define STAGE_BYTES 32768      /* A(8K) + B(24K) */
#define GEMM_SMEM  98304       /* 3 stages */

__device__ __forceinline__ uint32_t smem_u32(const void* p) {
    uint32_t a;
    asm("{ .reg .u64 t; cvta.to.shared.u64 t, %1; cvt.u32.u64 %0, t; }" : "=r"(a) : "l"(p));
    return a;
}

__device__ __forceinline__ void load_stage(char* smem, int t, int row0, int tid) {
    if (t >= NCHUNK) return;
    int k0 = t * 32;               /* f16 element offset within 512 */
    uint32_t s0 = smem_u32(smem + (t % 3) * STAGE_BYTES);

    /* A: 128 rows x 64B, 512 x 16B segs */
    #pragma unroll
    for (int j = 0; j < 2; j++) {
        int idx = j * 256 + tid;
        int row = idx >> 2, c = idx & 3;
        int gr = row0 + row;
        uint32_t sw = SW64((uint32_t)(row * 64 + c * 16));
        cp16(s0 + SM_A + sw, g_A + (size_t)gr * KDIM + k0 + c * 8, gr < N_NODES);
    }
    /* B: 384 rows x 64B, 1536 x 16B segs */
    #pragma unroll
    for (int j = 0; j < 6; j++) {
        int idx = j * 256 + tid;
        int row = idx >> 2, c = idx & 3;
        uint32_t sw = SW64((uint32_t)(row * 64 + c * 16));
        cp16(s0 + SM_B + sw, g_W + (size_t)row * KDIM + k0 + c * 8, 1);
    }
}

__global__ void __launch_bounds__(256, 1) gemm_mma_k(const float* __restrict__ bias,
                                                     float* __restrict__ out) {
    extern __shared__ char smem[];
    int tid  = threadIdx.x;
    int warp = tid >> 5, lane = tid & 31;
    int wm = warp >> 1, wn = warp & 1;     /* 4 x 2 warp grid, warp tile 32x64 */
    int row0 = blockIdx.x * 128;

    /* per-thread row scale factors for fold */
    float samp_r[2][2], satt_r[2][2];
    #pragma unroll
    for (int mt = 0; mt < 2; mt++)
        #pragma unroll
        for (int hi = 0; hi < 2; hi++) {
            int r = row0 + wm * 32 + mt * 16 + hi * 8 + (lane >> 2);
            samp_r[mt][hi] = (r < N_NODES) ? g_sc[2 * r] : 0.f;
            satt_r[mt][hi] = (r < N_NODES) ? g_sc[2 * r + 1] : 0.f;
        }

    float acc[2][8][4], oacc[2][8][4];
    #pragma unroll
    for (int i = 0; i < 2; i++)
        #pragma unroll
        for (int j = 0; j < 8; j++)
            #pragma unroll
            for (int k = 0; k < 4; k++) { acc[i][j][k] = 0.f; oacc[i][j][k] = 0.f; }

    load_stage(smem, 0, row0, tid);
    CP_COMMIT();
    load_stage(smem, 1, row0, tid);
    CP_COMMIT();

    for (int t = 0; t < NCHUNK; t++) {
        CP_WAIT1();
        __syncthreads();
        load_stage(smem, t + 2, row0, tid);
        CP_COMMIT();

        uint32_t s0 = smem_u32(smem + (t % 3) * STAGE_BYTES);

        /* A fragments: both kt halves, resident for the whole chunk */
        uint32_t af[2][2][4];
        #pragma unroll
        for (int kt = 0; kt < 2; kt++)
            #pragma unroll
            for (int mt = 0; mt < 2; mt++) {
                int r = wm * 32 + mt * 16 + (lane & 15);
                uint32_t sw = SW64((uint32_t)(r * 64 + kt * 32 + ((lane >> 4) * 16)));
                ldm_x4(af[kt][mt], s0 + SM_A + sw);
            }

        #pragma unroll
        for (int nb = 0; nb < 3; nb++) {
            #pragma unroll
            for (int kt = 0; kt < 2; kt++) {
                #pragma unroll
                for (int n4 = 0; n4 < 4; n4++) {
                    int n = nb * 128 + wn * 64 + n4 * 16 + (lane & 15);
                    uint32_t sw = SW64((uint32_t)(n * 64 + kt * 32 + ((lane >> 4) * 16)));
                    uint32_t bf[4];
                    ldm_x4(bf, s0 + SM_B + sw);
                    #pragma unroll
                    for (int mt = 0; mt < 2; mt++)
                        #pragma unroll
                        for (int hi = 0; hi < 2; hi++) {
                            int nt = n4 * 2 + hi;
                            mma16816(acc[mt][nt], af[kt][mt], bf[hi], bf[hi + 2]);
                        }
                }
            }
            /* fold this block's chunk-partial into oacc, reset acc */
            #pragma unroll
            for (int mt = 0; mt < 2; mt++)
                #pragma unroll
                for (int nt = 0; nt < 8; nt++) {
                    float s0f, s1f;
                    if (nb == 0)      { s0f = 1.f;            s1f = 1.f; }
                    else if (nb == 1) { s0f = samp_r[mt][0];  s1f = samp_r[mt][1]; }
                    else              { s0f = satt_r[mt][0];  s1f = satt_r[mt][1]; }
                    oacc[mt][nt][0] += s0f * acc[mt][nt][0];
                    oacc[mt][nt][1] += s0f * acc[mt][nt][1];
                    oacc[mt][nt][2] += s1f * acc[mt][nt][2];
                    oacc[mt][nt][3] += s1f * acc[mt][nt][3];
                    acc[mt][nt][0] = 0.f; acc[mt][nt][1] = 0.f;
                    acc[mt][nt][2] = 0.f; acc[mt][nt][3] = 0.f;
                }
        }
    }

    /* write out + bias */
    #pragma unroll
    for (int mt = 0; mt < 2; mt++)
        #pragma unroll
        for (int nt = 0; nt < 8; nt++) {
            int r = row0 + wm * 32 + mt * 16 + (lane >> 2);
            int c = wn * 64 + nt * 8 + (lane & 3) * 2;
            float b0 = bias[c], b1 = bias[c + 1];
            if (r < N_NODES)
                *(float2*)&out[(size_t)r * DDIM + c] =
                    make_float2(oacc[mt][nt][0] + b0, oacc[mt][nt][1] + b1);
            if (r + 8 < N_NODES)
                *(float2*)&out[(size_t)(r + 8) * DDIM + c] =
                    make_float2(oacc[mt][nt][2] + b0, oacc[mt][nt][3] + b1);
        }
}

/* ------------------- launch ---------------------------------------------- */
extern "C" void kernel_launch(void* const* d_in, const int* in_sizes, int n_in,
                              void* d_out, int out_size) {
    const float* x     = (const float*)d_in[0];
    const int*   index = (const int*)d_in[1];
    const float* W     = (const float*)d_in[2];
    const float* b     = (const float*)d_in[3];
    float*       out   = (float*)d_out;
    (void)in_sizes; (void)n_in; (void)out_size;

    cudaFuncSetAttribute(gemm_mma_k, cudaFuncAttributeMaxDynamicSharedMemorySize,
                         GEMM_SMEM);

    count_k<<<(N_EDGES + 255) / 256, 256>>>(index);
    scanA_k<<<SCAN_NBLK, SCAN_BLK>>>();
    scanB_k<<<1, 32>>>();
    scanC_k<<<SCAN_NBLK, SCAN_BLK>>>();
    scatter_k<<<(N_EDGES + 255) / 256, 256>>>(index);
    feat_k<<<(N_NODES * 32 + 255) / 256, 256>>>(x);
    wsplit_k<<<(NROWS_W * KDIM + 255) / 256, 256>>>(W);
    gemm_mma_k<<<(N_NODES + 127) / 128, 256, GEMM_SMEM>>>(b, out);
}